// round 7
// baseline (speedup 1.0000x reference)
#include <cuda_runtime.h>
#include <cuda_bf16.h>
#include <math.h>
#include <stdint.h>

#define BB 16
#define N_IN 6250
#define N_OUTC 25000
#define CCH 64
#define SS 9
#define NNZ 75000
#define NTILE 196                 // ceil(25000/128)
#define TT (BB * NTILE)           // 3136 work items
#define SP_BYTES (N_OUTC * SS * 4)  // 900000

// ---------------- device scratch ----------------
__device__ __align__(16) __nv_bfloat16 g_phi[(size_t)BB * N_OUTC * CCH];
__device__ __align__(16) __nv_bfloat16 g_plo[(size_t)BB * N_OUTC * CCH];
__device__ int   g_cnt[N_OUTC];
__device__ int   g_fillc[N_OUTC];
__device__ int   g_start[N_OUTC + 1];
__device__ int   g_csr_col[NNZ];
__device__ float g_csr_val[NNZ];
// unified split-W: slot s at s*16384 (hi), +8192 (lo); XOR-swizzled [k][n]
__device__ __align__(16) unsigned char g_Bsw[SS * 16384];

__device__ __forceinline__ uint32_t smem_u32(const void* p) {
    uint32_t a;
    asm("{ .reg .u64 t; cvta.to.shared.u64 t, %1; cvt.u32.u64 %0, t; }" : "=r"(a) : "l"(p));
    return a;
}
__device__ __forceinline__ uint32_t swz(uint32_t off) { return off ^ ((off >> 3) & 0x70); }

__device__ __forceinline__ void cp16(uint32_t dst, const void* src) {
    asm volatile("cp.async.cg.shared.global [%0], [%1], 16;" :: "r"(dst), "l"(src));
}
__device__ __forceinline__ void cp16z(uint32_t dst, const void* src, int srcsize) {
    asm volatile("cp.async.cg.shared.global [%0], [%1], 16, %2;"
                 :: "r"(dst), "l"(src), "r"(srcsize));
}
#define CP_COMMIT() asm volatile("cp.async.commit_group;" ::: "memory")
#define CP_WAIT1()  asm volatile("cp.async.wait_group 1;" ::: "memory")
#define CP_WAIT0()  asm volatile("cp.async.wait_group 0;" ::: "memory")

#define LDSM_X4(r0, r1, r2, r3, a) \
    asm volatile("ldmatrix.sync.aligned.m8n8.x4.shared.b16 {%0,%1,%2,%3}, [%4];" \
                 : "=r"(r0), "=r"(r1), "=r"(r2), "=r"(r3) : "r"(a))
#define LDSM_X4T(r0, r1, r2, r3, a) \
    asm volatile("ldmatrix.sync.aligned.m8n8.x4.trans.shared.b16 {%0,%1,%2,%3}, [%4];" \
                 : "=r"(r0), "=r"(r1), "=r"(r2), "=r"(r3) : "r"(a))

__device__ __forceinline__ void mma_bf16(float* d, const uint32_t* a, uint32_t b0, uint32_t b1) {
    asm volatile(
        "mma.sync.aligned.m16n8k16.row.col.f32.bf16.bf16.f32 "
        "{%0,%1,%2,%3}, {%4,%5,%6,%7}, {%8,%9}, {%0,%1,%2,%3};"
        : "+f"(d[0]), "+f"(d[1]), "+f"(d[2]), "+f"(d[3])
        : "r"(a[0]), "r"(a[1]), "r"(a[2]), "r"(a[3]), "r"(b0), "r"(b1));
}

// ---------------- CSR build ----------------
__global__ void k_zero_cnt() {
    int i = blockIdx.x * blockDim.x + threadIdx.x;
    if (i < N_OUTC) { g_cnt[i] = 0; g_fillc[i] = 0; }
}
__global__ void k_count(const int* __restrict__ row) {
    int i = blockIdx.x * blockDim.x + threadIdx.x;
    if (i < NNZ) atomicAdd(&g_cnt[row[i]], 1);
}
__global__ void k_scan() {
    __shared__ int wsum[32];
    __shared__ int carry;
    int tid = threadIdx.x, lane = tid & 31, w = tid >> 5;
    if (tid == 0) carry = 0;
    __syncthreads();
    const int NT2 = (N_OUTC + 1023) / 1024;
    for (int t = 0; t < NT2; ++t) {
        int i = t * 1024 + tid;
        int v = (i < N_OUTC) ? g_cnt[i] : 0;
        int sc = v;
#pragma unroll
        for (int o = 1; o < 32; o <<= 1) {
            int u = __shfl_up_sync(0xFFFFFFFFu, sc, o);
            if (lane >= o) sc += u;
        }
        if (lane == 31) wsum[w] = sc;
        __syncthreads();
        if (w == 0) {
            int ws = wsum[lane];
#pragma unroll
            for (int o = 1; o < 32; o <<= 1) {
                int u = __shfl_up_sync(0xFFFFFFFFu, ws, o);
                if (lane >= o) ws += u;
            }
            wsum[lane] = ws;
        }
        __syncthreads();
        int excl = sc - v + (w > 0 ? wsum[w - 1] : 0) + carry;
        if (i < N_OUTC) g_start[i] = excl;
        __syncthreads();
        if (tid == 1023) carry = excl + v;
        __syncthreads();
    }
    if (tid == 0) g_start[N_OUTC] = carry;
}
__global__ void k_fill(const float* __restrict__ vals,
                       const int* __restrict__ row,
                       const int* __restrict__ col) {
    int i = blockIdx.x * blockDim.x + threadIdx.x;
    if (i < NNZ) {
        int r = row[i];
        int pos = g_start[r] + atomicAdd(&g_fillc[r], 1);
        g_csr_col[pos] = col[i];
        g_csr_val[pos] = vals[i];
    }
}

// ---------------- W prep ----------------
__global__ void k_prepW(const float* __restrict__ W) {
    int i = blockIdx.x * blockDim.x + threadIdx.x;
    if (i >= SS * 64 * 64) return;
    int s = i / 4096, rem = i % 4096;
    int kk = rem / 64, n = rem % 64;
    float w = W[(size_t)(s * 64 + kk) * 64 + n];
    __nv_bfloat16 h = __float2bfloat16(w);
    float hf = __bfloat162float(h);
    __nv_bfloat16 l = __float2bfloat16(w - hf);
    uint32_t sw = swz((uint32_t)kk * 128 + (uint32_t)n * 2);
    *reinterpret_cast<__nv_bfloat16*>(g_Bsw + (size_t)s * 16384 + sw) = h;
    *reinterpret_cast<__nv_bfloat16*>(g_Bsw + (size_t)s * 16384 + 8192 + sw) = l;
}

// ---------------- pooling -> bf16 hi/lo planes ----------------
__global__ void k_pool(const float* __restrict__ x) {
    int b = blockIdx.y;
    int r = blockIdx.x * 4 + (threadIdx.x >> 6);
    int c = threadIdx.x & 63;
    if (r >= N_OUTC) return;
    int s0 = g_start[r], s1 = g_start[r + 1];
    const float* xb = x + (size_t)b * N_IN * CCH;
    float acc = 0.f;
    for (int j = s0; j < s1; ++j)
        acc += g_csr_val[j] * xb[(size_t)g_csr_col[j] * CCH + c];
    __nv_bfloat16 h = __float2bfloat16(acc);
    float hf = __bfloat162float(h);
    __nv_bfloat16 l = __float2bfloat16(acc - hf);
    size_t o = ((size_t)b * N_OUTC + r) * CCH + c;
    g_phi[o] = h;
    g_plo[o] = l;
}

// ---------------- persistent HMMA GEMM ----------------
// SMEM: [0,147456) W tiles; spw0/spw1 4608 each; A stages 2x32768
#define SM_B     0
#define SM_SPW0  147456
#define SM_SPW1  152064
#define SM_ST0   156672
#define SM_ST1   189440
#define ST_ALO   16384
#define SM_ALLOC (222208 + 1024)

__global__ __launch_bounds__(256, 1) void k_gemm(const int* __restrict__ sp,
                                                 const float* __restrict__ bias,
                                                 float* __restrict__ out) {
    extern __shared__ unsigned char smem_raw[];
    uint32_t raw = smem_u32(smem_raw);
    uint32_t sbase = (raw + 1023u) & ~1023u;
    unsigned char* smem = smem_raw + (sbase - raw);

    const int tid  = threadIdx.x;
    const int wid  = tid >> 5;
    const int lane = tid & 31;

    const int wm = wid & 3;
    const int wn = wid >> 2;
    const int q  = lane >> 3;
    const int lr = lane & 7;
    const int gid = lane >> 2;
    const int tig = lane & 3;
    const int grow = tid >> 3;      // 0..31
    const int gch  = tid & 7;

    // number of work items for this CTA
    int nt = 0;
    for (int tt = blockIdx.x; tt < TT; tt += gridDim.x) nt++;
    if (nt == 0) return;
    const int NS = nt * 9;

    // ---- load spiral-index block for local tile i (double-buffered, zfill-guarded)
    auto load_spw = [&](int i) {
        int tt = blockIdx.x + i * gridDim.x;
        uint32_t dst = sbase + SM_SPW0 + (uint32_t)(i & 1) * 4608u;
        long byte0 = (long)(tt % NTILE) * 128 * SS * 4;
        for (int c = tid; c < 288; c += 256) {
            long off = byte0 + (long)c * 16;
            long rem = (long)SP_BYTES - off;
            int sz = rem >= 16 ? 16 : (rem > 0 ? (int)rem : 0);
            const void* src = (const char*)sp + (off < SP_BYTES ? off : 0);
            cp16z(dst + (uint32_t)c * 16, src, sz);
        }
    };

    // ---- issue A-gather for flat step j into stage (j&1)
    auto load_A = [&](int j) {
        int i = j / 9, s = j - i * 9;
        int tt = blockIdx.x + i * gridDim.x;
        int bidx = tt / NTILE;
        const __nv_bfloat16* phib = g_phi + (size_t)bidx * N_OUTC * CCH;
        const __nv_bfloat16* plob = g_plo + (size_t)bidx * N_OUTC * CCH;
        const int* spwb = (const int*)(smem + SM_SPW0 + (i & 1) * 4608);
        uint32_t stg = sbase + SM_ST0 + (uint32_t)(j & 1) * 32768u;
#pragma unroll
        for (int it = 0; it < 4; ++it) {
            int row = it * 32 + grow;
            int g = spwb[row * SS + s];
            uint32_t d = swz((uint32_t)(row * 128 + gch * 16));
            cp16(stg + d, phib + (size_t)g * CCH + gch * 8);
            cp16(stg + ST_ALO + d, plob + (size_t)g * CCH + gch * 8);
        }
    };

    // ---- prologue: W tiles + spw(0); then A(0)+spw(1); A(1)
    for (int c = tid; c < 9216; c += 256)
        cp16(sbase + SM_B + (uint32_t)c * 16, g_Bsw + (size_t)c * 16);
    load_spw(0);
    CP_COMMIT();
    CP_WAIT0();
    __syncthreads();

    load_A(0);
    if (nt > 1) load_spw(1);
    CP_COMMIT();
    if (NS > 1) load_A(1);
    CP_COMMIT();

    float acc[2][4][4];
#pragma unroll
    for (int a = 0; a < 2; ++a)
#pragma unroll
        for (int b = 0; b < 4; ++b)
#pragma unroll
            for (int c = 0; c < 4; ++c) acc[a][b][c] = 0.f;

    const int arow_base = wm * 32 + (q & 1) * 8 + lr;
    const int achunk    = (q >> 1) * 16;
    const int bkrow     = (q & 1) * 8 + lr;
    const int bcol_base = (wn * 32 + (q >> 1) * 8) * 2;

    for (int j = 0; j < NS; ++j) {
        int i = j / 9, s = j - i * 9;
        CP_WAIT1();
        __syncthreads();

        uint32_t stg = sbase + SM_ST0 + (uint32_t)(j & 1) * 32768u;
        uint32_t bbase = sbase + SM_B + (uint32_t)s * 16384u;
#pragma unroll
        for (int kk = 0; kk < 4; ++kk) {
            uint32_t ah[2][4], al[2][4], bh[2][4], bl[2][4];
#pragma unroll
            for (int mt = 0; mt < 2; ++mt) {
                uint32_t off = swz((uint32_t)((arow_base + mt * 16) * 128 + kk * 32 + achunk));
                LDSM_X4(ah[mt][0], ah[mt][1], ah[mt][2], ah[mt][3], stg + off);
                LDSM_X4(al[mt][0], al[mt][1], al[mt][2], al[mt][3], stg + ST_ALO + off);
            }
#pragma unroll
            for (int t = 0; t < 2; ++t) {
                uint32_t off = swz((uint32_t)((kk * 16 + bkrow) * 128 + bcol_base + t * 32));
                LDSM_X4T(bh[t][0], bh[t][1], bh[t][2], bh[t][3], bbase + off);
                LDSM_X4T(bl[t][0], bl[t][1], bl[t][2], bl[t][3], bbase + 8192 + off);
            }
#pragma unroll
            for (int mt = 0; mt < 2; ++mt)
#pragma unroll
                for (int ni = 0; ni < 4; ++ni) {
                    uint32_t bh0 = bh[ni >> 1][(ni & 1) * 2 + 0];
                    uint32_t bh1 = bh[ni >> 1][(ni & 1) * 2 + 1];
                    uint32_t bl0 = bl[ni >> 1][(ni & 1) * 2 + 0];
                    uint32_t bl1 = bl[ni >> 1][(ni & 1) * 2 + 1];
                    mma_bf16(acc[mt][ni], ah[mt], bh0, bh1);
                    mma_bf16(acc[mt][ni], ah[mt], bl0, bl1);
                    mma_bf16(acc[mt][ni], al[mt], bh0, bh1);
                }
        }

        // ---- epilogue at last slot of tile
        if (s == 8) {
            int tt = blockIdx.x + i * gridDim.x;
            int bidx = tt / NTILE;
            int n0 = (tt % NTILE) * 128;
#pragma unroll
            for (int mt = 0; mt < 2; ++mt)
#pragma unroll
                for (int half = 0; half < 2; ++half) {
                    int r = n0 + wm * 32 + mt * 16 + gid + half * 8;
                    if (r < N_OUTC) {
                        float* orow = out + ((size_t)bidx * N_OUTC + r) * 64;
#pragma unroll
                        for (int ni = 0; ni < 4; ++ni) {
                            int col = wn * 32 + ni * 8 + tig * 2;
                            float2 bb = *reinterpret_cast<const float2*>(bias + col);
                            float vx = acc[mt][ni][half * 2 + 0] + bb.x;
                            float vy = acc[mt][ni][half * 2 + 1] + bb.y;
                            vx = vx > 0.f ? vx : expm1f(vx);
                            vy = vy > 0.f ? vy : expm1f(vy);
                            *reinterpret_cast<float2*>(orow + col) = make_float2(vx, vy);
                        }
                    }
                }
#pragma unroll
            for (int a = 0; a < 2; ++a)
#pragma unroll
                for (int b = 0; b < 4; ++b)
#pragma unroll
                    for (int c = 0; c < 4; ++c) acc[a][b][c] = 0.f;
        }

        // ---- issue lookahead loads
        __syncthreads();
        if (j + 2 < NS) load_A(j + 2);
        if (s == 7 && i + 2 < nt) load_spw(i + 2);
        CP_COMMIT();
    }
}

// ---------------- launcher ----------------
extern "C" void kernel_launch(void* const* d_in, const int* in_sizes, int n_in,
                              void* d_out, int out_size) {
    const float* x    = (const float*)d_in[0];
    const float* tval = (const float*)d_in[1];
    const int*   trow = (const int*)d_in[2];
    const int*   tcol = (const int*)d_in[3];
    const int*   sp   = (const int*)d_in[4];
    const float* W    = (const float*)d_in[5];
    const float* bias = (const float*)d_in[6];
    float* out = (float*)d_out;

    cudaFuncSetAttribute(k_gemm, cudaFuncAttributeMaxDynamicSharedMemorySize, SM_ALLOC);

    k_zero_cnt<<<(N_OUTC + 255) / 256, 256>>>();
    k_count<<<(NNZ + 255) / 256, 256>>>(trow);
    k_scan<<<1, 1024>>>();
    k_fill<<<(NNZ + 255) / 256, 256>>>(tval, trow, tcol);
    k_prepW<<<(SS * 64 * 64 + 255) / 256, 256>>>(W);

    dim3 pg((N_OUTC + 3) / 4, BB);
    k_pool<<<pg, 256>>>(x);

    k_gemm<<<148, 256, SM_ALLOC>>>(sp, bias, out);
}

// round 8
// speedup vs baseline: 1.4243x; 1.4243x over previous
#include <cuda_runtime.h>
#include <cuda_fp16.h>
#include <math.h>
#include <stdint.h>

#define BB 16
#define N_IN 6250
#define N_OUTC 25000
#define CCH 64
#define SS 9
#define NNZ 75000

// ---------------- device scratch ----------------
__device__ __align__(16) __half g_phi[(size_t)BB * N_OUTC * CCH]; // pooled hi plane (fp16)
__device__ __align__(16) __half g_plo[(size_t)BB * N_OUTC * CCH]; // pooled lo plane (fp16)
__device__ int   g_cnt[N_OUTC];
__device__ int   g_fillc[N_OUTC];
__device__ int   g_start[N_OUTC + 1];
__device__ int   g_csr_col[NNZ];
__device__ float g_csr_val[NNZ];
// per-slot 64(k)x64(n) fp16 tiles, XOR-swizzled [k][n] layout
__device__ __align__(16) unsigned char g_Bh[SS * 8192];

__device__ __forceinline__ uint32_t smem_u32(const void* p) {
    uint32_t a;
    asm("{ .reg .u64 t; cvta.to.shared.u64 t, %1; cvt.u32.u64 %0, t; }" : "=r"(a) : "l"(p));
    return a;
}
__device__ __forceinline__ uint32_t swz(uint32_t off) { return off ^ ((off >> 3) & 0x70); }

__device__ __forceinline__ void cp16(uint32_t dst, const void* src) {
    asm volatile("cp.async.cg.shared.global [%0], [%1], 16;" :: "r"(dst), "l"(src));
}
#define CP_COMMIT() asm volatile("cp.async.commit_group;" ::: "memory")
#define CP_WAIT1()  asm volatile("cp.async.wait_group 1;" ::: "memory")

#define LDSM_X4(r0, r1, r2, r3, a) \
    asm volatile("ldmatrix.sync.aligned.m8n8.x4.shared.b16 {%0,%1,%2,%3}, [%4];" \
                 : "=r"(r0), "=r"(r1), "=r"(r2), "=r"(r3) : "r"(a))
#define LDSM_X4T(r0, r1, r2, r3, a) \
    asm volatile("ldmatrix.sync.aligned.m8n8.x4.trans.shared.b16 {%0,%1,%2,%3}, [%4];" \
                 : "=r"(r0), "=r"(r1), "=r"(r2), "=r"(r3) : "r"(a))

__device__ __forceinline__ void mma_f16(float* d, const uint32_t* a, uint32_t b0, uint32_t b1) {
    asm volatile(
        "mma.sync.aligned.m16n8k16.row.col.f32.f16.f16.f32 "
        "{%0,%1,%2,%3}, {%4,%5,%6,%7}, {%8,%9}, {%0,%1,%2,%3};"
        : "+f"(d[0]), "+f"(d[1]), "+f"(d[2]), "+f"(d[3])
        : "r"(a[0]), "r"(a[1]), "r"(a[2]), "r"(a[3]), "r"(b0), "r"(b1));
}

// ---------------- CSR build ----------------
__global__ void k_zero_cnt() {
    int i = blockIdx.x * blockDim.x + threadIdx.x;
    if (i < N_OUTC) { g_cnt[i] = 0; g_fillc[i] = 0; }
}
__global__ void k_count(const int* __restrict__ row) {
    int i = blockIdx.x * blockDim.x + threadIdx.x;
    if (i < NNZ) atomicAdd(&g_cnt[row[i]], 1);
}
__global__ void k_scan() {
    __shared__ int wsum[32];
    __shared__ int carry;
    int tid = threadIdx.x, lane = tid & 31, w = tid >> 5;
    if (tid == 0) carry = 0;
    __syncthreads();
    const int NT = (N_OUTC + 1023) / 1024;
    for (int t = 0; t < NT; ++t) {
        int i = t * 1024 + tid;
        int v = (i < N_OUTC) ? g_cnt[i] : 0;
        int sc = v;
#pragma unroll
        for (int o = 1; o < 32; o <<= 1) {
            int u = __shfl_up_sync(0xFFFFFFFFu, sc, o);
            if (lane >= o) sc += u;
        }
        if (lane == 31) wsum[w] = sc;
        __syncthreads();
        if (w == 0) {
            int ws = wsum[lane];
#pragma unroll
            for (int o = 1; o < 32; o <<= 1) {
                int u = __shfl_up_sync(0xFFFFFFFFu, ws, o);
                if (lane >= o) ws += u;
            }
            wsum[lane] = ws;
        }
        __syncthreads();
        int excl = sc - v + (w > 0 ? wsum[w - 1] : 0) + carry;
        if (i < N_OUTC) g_start[i] = excl;
        __syncthreads();
        if (tid == 1023) carry = excl + v;
        __syncthreads();
    }
    if (tid == 0) g_start[N_OUTC] = carry;
}
__global__ void k_fill(const float* __restrict__ vals,
                       const int* __restrict__ row,
                       const int* __restrict__ col) {
    int i = blockIdx.x * blockDim.x + threadIdx.x;
    if (i < NNZ) {
        int r = row[i];
        int pos = g_start[r] + atomicAdd(&g_fillc[r], 1);
        g_csr_col[pos] = col[i];
        g_csr_val[pos] = vals[i];
    }
}

// ---------------- W prep: [k][n] fp16, XOR-swizzled ----------------
__global__ void k_prepW(const float* __restrict__ W) {
    int i = blockIdx.x * blockDim.x + threadIdx.x;
    if (i >= SS * 64 * 64) return;
    int s = i / 4096, rem = i % 4096;
    int kk = rem / 64, n = rem % 64;
    float w = W[(size_t)(s * 64 + kk) * 64 + n];
    uint32_t sw = swz((uint32_t)kk * 128 + (uint32_t)n * 2);
    *reinterpret_cast<__half*>(g_Bh + (size_t)s * 8192 + sw) = __float2half_rn(w);
}

// ---------------- pooling -> fp16 hi/lo planes ----------------
__global__ void k_pool(const float* __restrict__ x) {
    int b = blockIdx.y;
    int r = blockIdx.x * 4 + (threadIdx.x >> 6);
    int c = threadIdx.x & 63;
    if (r >= N_OUTC) return;
    int s0 = g_start[r], s1 = g_start[r + 1];
    const float* xb = x + (size_t)b * N_IN * CCH;
    float acc = 0.f;
    for (int j = s0; j < s1; ++j)
        acc += g_csr_val[j] * xb[(size_t)g_csr_col[j] * CCH + c];
    __half h = __float2half_rn(acc);
    __half l = __float2half_rn(acc - __half2float(h));
    size_t o = ((size_t)b * N_OUTC + r) * CCH + c;
    g_phi[o] = h;
    g_plo[o] = l;
}

// ---------------- HMMA GEMM: 2-stage cp.async pipeline, fp16 split-A x fp16 B ----------------
#define SM_SPW     0            // 128*9*4 = 4608
#define SM_STAGE0  5120
#define ST_AHI     0            // 16384
#define ST_ALO     16384        // 16384
#define ST_B       32768        // 8192
#define ST_BYTES   40960
#define SM_ALLOC   (SM_STAGE0 + 2 * ST_BYTES + 1024)

__global__ __launch_bounds__(256, 2) void k_gemm(const int* __restrict__ sp,
                                                 const float* __restrict__ bias,
                                                 float* __restrict__ out) {
    extern __shared__ unsigned char smem_raw[];
    uint32_t raw = smem_u32(smem_raw);
    uint32_t sbase = (raw + 1023u) & ~1023u;
    unsigned char* smem = smem_raw + (sbase - raw);

    const int tid  = threadIdx.x;
    const int wid  = tid >> 5;
    const int lane = tid & 31;
    const int bidx = blockIdx.y;
    const int n0   = blockIdx.x * 128;

    const int wm = wid & 3;
    const int wn = wid >> 2;
    const int q  = lane >> 3;
    const int lr = lane & 7;
    const int gid = lane >> 2;
    const int tig = lane & 3;

    // stage spiral indices
    int* spw = reinterpret_cast<int*>(smem + SM_SPW);
    for (int i = tid; i < 128 * SS; i += 256) {
        int r = n0 + i / SS;
        spw[i] = (r < N_OUTC) ? sp[(size_t)r * SS + (i % SS)] : 0;
    }
    __syncthreads();

    const __half* phib = g_phi + (size_t)bidx * N_OUTC * CCH;
    const __half* plob = g_plo + (size_t)bidx * N_OUTC * CCH;

    const int grow = tid >> 3;      // 8 threads per 128B row
    const int gch  = tid & 7;

    auto load_stage = [&](int s, int buf) {
        uint32_t stg = sbase + SM_STAGE0 + buf * ST_BYTES;
#pragma unroll
        for (int it = 0; it < 4; ++it) {
            int row = it * 32 + grow;
            int g = spw[row * SS + s];
            uint32_t d = swz((uint32_t)(row * 128 + gch * 16));
            cp16(stg + ST_AHI + d, phib + (size_t)g * CCH + gch * 8);
            cp16(stg + ST_ALO + d, plob + (size_t)g * CCH + gch * 8);
        }
#pragma unroll
        for (int it = 0; it < 2; ++it) {
            uint32_t o = (uint32_t)(it * 256 + tid) * 16;
            if (o < 8192)
                cp16(stg + ST_B + o, g_Bh + (size_t)s * 8192 + o);
        }
    };

    float acc[2][4][4];
#pragma unroll
    for (int a = 0; a < 2; ++a)
#pragma unroll
        for (int b = 0; b < 4; ++b)
#pragma unroll
            for (int c = 0; c < 4; ++c) acc[a][b][c] = 0.f;

    const int arow_base = wm * 32 + (q & 1) * 8 + lr;
    const int achunk    = (q >> 1) * 16;
    const int bkrow     = (q & 1) * 8 + lr;
    const int bcol_base = (wn * 32 + (q >> 1) * 8) * 2;

    load_stage(0, 0); CP_COMMIT();
    load_stage(1, 1); CP_COMMIT();

    for (int s = 0; s < SS; ++s) {
        CP_WAIT1();
        __syncthreads();

        uint32_t stg = sbase + SM_STAGE0 + (s & 1) * ST_BYTES;
#pragma unroll
        for (int kk = 0; kk < 4; ++kk) {
            uint32_t ah[2][4], al[2][4], bf[2][4];
#pragma unroll
            for (int mt = 0; mt < 2; ++mt) {
                uint32_t off = swz((uint32_t)((arow_base + mt * 16) * 128 + kk * 32 + achunk));
                LDSM_X4(ah[mt][0], ah[mt][1], ah[mt][2], ah[mt][3], stg + ST_AHI + off);
                LDSM_X4(al[mt][0], al[mt][1], al[mt][2], al[mt][3], stg + ST_ALO + off);
            }
#pragma unroll
            for (int t = 0; t < 2; ++t) {
                uint32_t off = swz((uint32_t)((kk * 16 + bkrow) * 128 + bcol_base + t * 32));
                LDSM_X4T(bf[t][0], bf[t][1], bf[t][2], bf[t][3], stg + ST_B + off);
            }
#pragma unroll
            for (int mt = 0; mt < 2; ++mt)
#pragma unroll
                for (int ni = 0; ni < 4; ++ni) {
                    uint32_t b0 = bf[ni >> 1][(ni & 1) * 2 + 0];
                    uint32_t b1 = bf[ni >> 1][(ni & 1) * 2 + 1];
                    mma_f16(acc[mt][ni], ah[mt], b0, b1);
                    mma_f16(acc[mt][ni], al[mt], b0, b1);
                }
        }
        __syncthreads();
        if (s + 2 < SS) load_stage(s + 2, s & 1);
        CP_COMMIT();
    }

    // ---- epilogue: bias + ELU
#pragma unroll
    for (int mt = 0; mt < 2; ++mt) {
#pragma unroll
        for (int half = 0; half < 2; ++half) {
            int r = n0 + wm * 32 + mt * 16 + gid + half * 8;
            if (r < N_OUTC) {
                float* orow = out + ((size_t)bidx * N_OUTC + r) * 64;
#pragma unroll
                for (int ni = 0; ni < 4; ++ni) {
                    int col = wn * 32 + ni * 8 + tig * 2;
                    float2 bb = *reinterpret_cast<const float2*>(bias + col);
                    float vx = acc[mt][ni][half * 2 + 0] + bb.x;
                    float vy = acc[mt][ni][half * 2 + 1] + bb.y;
                    vx = vx > 0.f ? vx : expm1f(vx);
                    vy = vy > 0.f ? vy : expm1f(vy);
                    *reinterpret_cast<float2*>(orow + col) = make_float2(vx, vy);
                }
            }
        }
    }
}

// ---------------- launcher ----------------
extern "C" void kernel_launch(void* const* d_in, const int* in_sizes, int n_in,
                              void* d_out, int out_size) {
    const float* x    = (const float*)d_in[0];
    const float* tval = (const float*)d_in[1];
    const int*   trow = (const int*)d_in[2];
    const int*   tcol = (const int*)d_in[3];
    const int*   sp   = (const int*)d_in[4];
    const float* W    = (const float*)d_in[5];
    const float* bias = (const float*)d_in[6];
    float* out = (float*)d_out;

    cudaFuncSetAttribute(k_gemm, cudaFuncAttributeMaxDynamicSharedMemorySize, SM_ALLOC);

    k_zero_cnt<<<(N_OUTC + 255) / 256, 256>>>();
    k_count<<<(NNZ + 255) / 256, 256>>>(trow);
    k_scan<<<1, 1024>>>();
    k_fill<<<(NNZ + 255) / 256, 256>>>(tval, trow, tcol);
    k_prepW<<<(SS * 64 * 64 + 255) / 256, 256>>>(W);

    dim3 pg((N_OUTC + 3) / 4, BB);
    k_pool<<<pg, 256>>>(x);

    dim3 gg((N_OUTC + 127) / 128, BB);
    k_gemm<<<gg, 256, SM_ALLOC>>>(sp, bias, out);
}

// round 9
// speedup vs baseline: 1.6317x; 1.1456x over previous
#include <cuda_runtime.h>
#include <cuda_fp16.h>
#include <math.h>
#include <stdint.h>

#define BB 16
#define N_IN 6250
#define N_OUTC 25000
#define CCH 64
#define SS 9
#define NNZ 75000

// ---------------- device scratch ----------------
__device__ __align__(16) __half g_phi[(size_t)BB * N_OUTC * CCH]; // pooled hi plane (fp16)
__device__ __align__(16) __half g_plo[(size_t)BB * N_OUTC * CCH]; // pooled lo plane (fp16)
__device__ int   g_cnt[N_OUTC];
__device__ int   g_fillc[N_OUTC];
__device__ int   g_startv[N_OUTC];
__device__ int   g_total;
__device__ int   g_csr_col[NNZ];
__device__ float g_csr_val[NNZ];
// per-slot 64(k)x64(n) fp16 tiles, XOR-swizzled [k][n] layout
__device__ __align__(16) unsigned char g_Bh[SS * 8192];

__device__ __forceinline__ uint32_t smem_u32(const void* p) {
    uint32_t a;
    asm("{ .reg .u64 t; cvta.to.shared.u64 t, %1; cvt.u32.u64 %0, t; }" : "=r"(a) : "l"(p));
    return a;
}
__device__ __forceinline__ uint32_t swz(uint32_t off) { return off ^ ((off >> 3) & 0x70); }

__device__ __forceinline__ void cp16(uint32_t dst, const void* src) {
    asm volatile("cp.async.cg.shared.global [%0], [%1], 16;" :: "r"(dst), "l"(src));
}
#define CP_COMMIT() asm volatile("cp.async.commit_group;" ::: "memory")
#define CP_WAIT1()  asm volatile("cp.async.wait_group 1;" ::: "memory")

#define LDSM_X4(r0, r1, r2, r3, a) \
    asm volatile("ldmatrix.sync.aligned.m8n8.x4.shared.b16 {%0,%1,%2,%3}, [%4];" \
                 : "=r"(r0), "=r"(r1), "=r"(r2), "=r"(r3) : "r"(a))
#define LDSM_X4T(r0, r1, r2, r3, a) \
    asm volatile("ldmatrix.sync.aligned.m8n8.x4.trans.shared.b16 {%0,%1,%2,%3}, [%4];" \
                 : "=r"(r0), "=r"(r1), "=r"(r2), "=r"(r3) : "r"(a))

__device__ __forceinline__ void mma_f16_f32(float* d, const uint32_t* a, uint32_t b0, uint32_t b1) {
    asm volatile(
        "mma.sync.aligned.m16n8k16.row.col.f32.f16.f16.f32 "
        "{%0,%1,%2,%3}, {%4,%5,%6,%7}, {%8,%9}, {%0,%1,%2,%3};"
        : "+f"(d[0]), "+f"(d[1]), "+f"(d[2]), "+f"(d[3])
        : "r"(a[0]), "r"(a[1]), "r"(a[2]), "r"(a[3]), "r"(b0), "r"(b1));
}
// fp16 accumulator variant (lo-correction path)
__device__ __forceinline__ void mma_f16_f16(uint32_t* d, const uint32_t* a, uint32_t b0, uint32_t b1) {
    asm volatile(
        "mma.sync.aligned.m16n8k16.row.col.f16.f16.f16.f16 "
        "{%0,%1}, {%2,%3,%4,%5}, {%6,%7}, {%0,%1};"
        : "+r"(d[0]), "+r"(d[1])
        : "r"(a[0]), "r"(a[1]), "r"(a[2]), "r"(a[3]), "r"(b0), "r"(b1));
}

// ---------------- CSR build ----------------
__global__ void k_zero_cnt() {
    int i = blockIdx.x * blockDim.x + threadIdx.x;
    if (i < N_OUTC) { g_cnt[i] = 0; g_fillc[i] = 0; }
    if (i == 0) g_total = 0;
}
__global__ void k_count(const int* __restrict__ row) {
    int i = blockIdx.x * blockDim.x + threadIdx.x;
    if (i < NNZ) atomicAdd(&g_cnt[row[i]], 1);
}
// unordered-but-disjoint segment assignment (replaces prefix scan)
__global__ void k_starts() {
    int i = blockIdx.x * blockDim.x + threadIdx.x;
    if (i < N_OUTC) {
        int c = g_cnt[i];
        g_startv[i] = c ? atomicAdd(&g_total, c) : 0;
    }
}
__global__ void k_fill(const float* __restrict__ vals,
                       const int* __restrict__ row,
                       const int* __restrict__ col) {
    int i = blockIdx.x * blockDim.x + threadIdx.x;
    if (i < NNZ) {
        int r = row[i];
        int pos = g_startv[r] + atomicAdd(&g_fillc[r], 1);
        g_csr_col[pos] = col[i];
        g_csr_val[pos] = vals[i];
    }
}

// ---------------- W prep: [k][n] fp16, XOR-swizzled ----------------
__global__ void k_prepW(const float* __restrict__ W) {
    int i = blockIdx.x * blockDim.x + threadIdx.x;
    if (i >= SS * 64 * 64) return;
    int s = i / 4096, rem = i % 4096;
    int kk = rem / 64, n = rem % 64;
    float w = W[(size_t)(s * 64 + kk) * 64 + n];
    uint32_t sw = swz((uint32_t)kk * 128 + (uint32_t)n * 2);
    *reinterpret_cast<__half*>(g_Bh + (size_t)s * 8192 + sw) = __float2half_rn(w);
}

// ---------------- pooling -> fp16 hi/lo planes (2 cols/thread, half2 stores) ----------------
__global__ void k_pool(const float* __restrict__ x) {
    int b = blockIdx.y;
    int r = blockIdx.x * 8 + (threadIdx.x >> 5);
    int c2 = (threadIdx.x & 31) * 2;
    if (r >= N_OUTC) return;
    int s0 = g_startv[r], s1 = s0 + g_cnt[r];
    const float* xb = x + (size_t)b * N_IN * CCH;
    float ax = 0.f, ay = 0.f;
    for (int j = s0; j < s1; ++j) {
        float v = g_csr_val[j];
        float2 xx = *reinterpret_cast<const float2*>(xb + (size_t)g_csr_col[j] * CCH + c2);
        ax += v * xx.x;
        ay += v * xx.y;
    }
    __half hx = __float2half_rn(ax), hy = __float2half_rn(ay);
    __half lx = __float2half_rn(ax - __half2float(hx));
    __half ly = __float2half_rn(ay - __half2float(hy));
    size_t o = ((size_t)b * N_OUTC + r) * CCH + c2;
    *reinterpret_cast<__half2*>(&g_phi[o]) = __halves2half2(hx, hy);
    *reinterpret_cast<__half2*>(&g_plo[o]) = __halves2half2(lx, ly);
}

// ---------------- HMMA GEMM: 2-stage cp.async pipeline, fp16 split-A x fp16 B ----------------
#define SM_SPW     0            // 128*9*4 = 4608
#define SM_STAGE0  5120
#define ST_AHI     0            // 16384
#define ST_ALO     16384        // 16384
#define ST_B       32768        // 8192
#define ST_BYTES   40960
#define SM_ALLOC   (SM_STAGE0 + 2 * ST_BYTES + 1024)

__global__ __launch_bounds__(256, 2) void k_gemm(const int* __restrict__ sp,
                                                 const float* __restrict__ bias,
                                                 float* __restrict__ out) {
    extern __shared__ unsigned char smem_raw[];
    uint32_t raw = smem_u32(smem_raw);
    uint32_t sbase = (raw + 1023u) & ~1023u;
    unsigned char* smem = smem_raw + (sbase - raw);

    const int tid  = threadIdx.x;
    const int wid  = tid >> 5;
    const int lane = tid & 31;
    const int bidx = blockIdx.y;
    const int n0   = blockIdx.x * 128;

    const int wm = wid & 3;
    const int wn = wid >> 2;
    const int q  = lane >> 3;
    const int lr = lane & 7;
    const int gid = lane >> 2;
    const int tig = lane & 3;

    // stage spiral indices
    int* spw = reinterpret_cast<int*>(smem + SM_SPW);
    for (int i = tid; i < 128 * SS; i += 256) {
        int r = n0 + i / SS;
        spw[i] = (r < N_OUTC) ? sp[(size_t)r * SS + (i % SS)] : 0;
    }
    __syncthreads();

    const __half* phib = g_phi + (size_t)bidx * N_OUTC * CCH;
    const __half* plob = g_plo + (size_t)bidx * N_OUTC * CCH;

    const int grow = tid >> 3;      // 8 threads per 128B row
    const int gch  = tid & 7;

    auto load_stage = [&](int s, int buf) {
        uint32_t stg = sbase + SM_STAGE0 + buf * ST_BYTES;
#pragma unroll
        for (int it = 0; it < 4; ++it) {
            int row = it * 32 + grow;
            int g = spw[row * SS + s];
            uint32_t d = swz((uint32_t)(row * 128 + gch * 16));
            cp16(stg + ST_AHI + d, phib + (size_t)g * CCH + gch * 8);
            cp16(stg + ST_ALO + d, plob + (size_t)g * CCH + gch * 8);
        }
#pragma unroll
        for (int it = 0; it < 2; ++it) {
            uint32_t o = (uint32_t)(it * 256 + tid) * 16;
            if (o < 8192)
                cp16(stg + ST_B + o, g_Bh + (size_t)s * 8192 + o);
        }
    };

    float    acch[2][4][4];   // hi product, f32 acc
    uint32_t accl[2][4][2];   // lo product, f16x2 acc
#pragma unroll
    for (int a = 0; a < 2; ++a)
#pragma unroll
        for (int b = 0; b < 4; ++b) {
#pragma unroll
            for (int c = 0; c < 4; ++c) acch[a][b][c] = 0.f;
            accl[a][b][0] = 0u; accl[a][b][1] = 0u;
        }

    const int arow_base = wm * 32 + (q & 1) * 8 + lr;
    const int achunk    = (q >> 1) * 16;
    const int bkrow     = (q & 1) * 8 + lr;
    const int bcol_base = (wn * 32 + (q >> 1) * 8) * 2;

    load_stage(0, 0); CP_COMMIT();
    load_stage(1, 1); CP_COMMIT();

    for (int s = 0; s < SS; ++s) {
        CP_WAIT1();
        __syncthreads();

        uint32_t stg = sbase + SM_STAGE0 + (s & 1) * ST_BYTES;
#pragma unroll
        for (int kk = 0; kk < 4; ++kk) {
            uint32_t ah[2][4], al[2][4], bf[2][4];
#pragma unroll
            for (int mt = 0; mt < 2; ++mt) {
                uint32_t off = swz((uint32_t)((arow_base + mt * 16) * 128 + kk * 32 + achunk));
                LDSM_X4(ah[mt][0], ah[mt][1], ah[mt][2], ah[mt][3], stg + ST_AHI + off);
                LDSM_X4(al[mt][0], al[mt][1], al[mt][2], al[mt][3], stg + ST_ALO + off);
            }
#pragma unroll
            for (int t = 0; t < 2; ++t) {
                uint32_t off = swz((uint32_t)((kk * 16 + bkrow) * 128 + bcol_base + t * 32));
                LDSM_X4T(bf[t][0], bf[t][1], bf[t][2], bf[t][3], stg + ST_B + off);
            }
#pragma unroll
            for (int mt = 0; mt < 2; ++mt)
#pragma unroll
                for (int ni = 0; ni < 4; ++ni) {
                    uint32_t b0 = bf[ni >> 1][(ni & 1) * 2 + 0];
                    uint32_t b1 = bf[ni >> 1][(ni & 1) * 2 + 1];
                    mma_f16_f32(acch[mt][ni], ah[mt], b0, b1);
                    mma_f16_f16(accl[mt][ni], al[mt], b0, b1);
                }
        }
        __syncthreads();
        if (s + 2 < SS) load_stage(s + 2, s & 1);
        CP_COMMIT();
    }

    // ---- epilogue: hi + lo + bias, ELU
#pragma unroll
    for (int mt = 0; mt < 2; ++mt) {
#pragma unroll
        for (int half = 0; half < 2; ++half) {
            int r = n0 + wm * 32 + mt * 16 + gid + half * 8;
            if (r < N_OUTC) {
                float* orow = out + ((size_t)bidx * N_OUTC + r) * 64;
#pragma unroll
                for (int ni = 0; ni < 4; ++ni) {
                    int col = wn * 32 + ni * 8 + tig * 2;
                    float2 bb = *reinterpret_cast<const float2*>(bias + col);
                    float2 lo = __half22float2(*reinterpret_cast<const __half2*>(&accl[mt][ni][half]));
                    float vx = acch[mt][ni][half * 2 + 0] + lo.x + bb.x;
                    float vy = acch[mt][ni][half * 2 + 1] + lo.y + bb.y;
                    vx = vx > 0.f ? vx : expm1f(vx);
                    vy = vy > 0.f ? vy : expm1f(vy);
                    *reinterpret_cast<float2*>(orow + col) = make_float2(vx, vy);
                }
            }
        }
    }
}

// ---------------- launcher ----------------
extern "C" void kernel_launch(void* const* d_in, const int* in_sizes, int n_in,
                              void* d_out, int out_size) {
    const float* x    = (const float*)d_in[0];
    const float* tval = (const float*)d_in[1];
    const int*   trow = (const int*)d_in[2];
    const int*   tcol = (const int*)d_in[3];
    const int*   sp   = (const int*)d_in[4];
    const float* W    = (const float*)d_in[5];
    const float* bias = (const float*)d_in[6];
    float* out = (float*)d_out;

    cudaFuncSetAttribute(k_gemm, cudaFuncAttributeMaxDynamicSharedMemorySize, SM_ALLOC);

    k_zero_cnt<<<(N_OUTC + 255) / 256, 256>>>();
    k_count<<<(NNZ + 255) / 256, 256>>>(trow);
    k_starts<<<(N_OUTC + 255) / 256, 256>>>();
    k_fill<<<(NNZ + 255) / 256, 256>>>(tval, trow, tcol);
    k_prepW<<<(SS * 64 * 64 + 255) / 256, 256>>>(W);

    dim3 pg((N_OUTC + 7) / 8, BB);
    k_pool<<<pg, 256>>>(x);

    dim3 gg((N_OUTC + 127) / 128, BB);
    k_gemm<<<gg, 256, SM_ALLOC>>>(sp, bias, out);
}

// round 10
// speedup vs baseline: 2.0364x; 1.2480x over previous
#include <cuda_runtime.h>
#include <cuda_fp16.h>
#include <math.h>
#include <stdint.h>

#define BB 16
#define N_IN 6250
#define N_OUTC 25000
#define CCH 64
#define SS 9
#define NNZ 75000

// ---------------- device scratch ----------------
__device__ __align__(16) __half g_ph[(size_t)BB * N_OUTC * CCH]; // pooled fp16 plane
__device__ int   g_cnt[N_OUTC];
__device__ int   g_fillc[N_OUTC];
__device__ int   g_startv[N_OUTC];
__device__ int   g_total;
__device__ int   g_csr_col[NNZ];
__device__ float g_csr_val[NNZ];
// per-slot 64(k)x64(n) fp16 tiles, XOR-swizzled [k][n] layout
__device__ __align__(16) unsigned char g_Bh[SS * 8192];

__device__ __forceinline__ uint32_t smem_u32(const void* p) {
    uint32_t a;
    asm("{ .reg .u64 t; cvta.to.shared.u64 t, %1; cvt.u32.u64 %0, t; }" : "=r"(a) : "l"(p));
    return a;
}
__device__ __forceinline__ uint32_t swz(uint32_t off) { return off ^ ((off >> 3) & 0x70); }

__device__ __forceinline__ void cp16(uint32_t dst, const void* src) {
    asm volatile("cp.async.cg.shared.global [%0], [%1], 16;" :: "r"(dst), "l"(src));
}
#define CP_COMMIT() asm volatile("cp.async.commit_group;" ::: "memory")
#define CP_WAIT2()  asm volatile("cp.async.wait_group 2;" ::: "memory")

#define LDSM_X4(r0, r1, r2, r3, a) \
    asm volatile("ldmatrix.sync.aligned.m8n8.x4.shared.b16 {%0,%1,%2,%3}, [%4];" \
                 : "=r"(r0), "=r"(r1), "=r"(r2), "=r"(r3) : "r"(a))
#define LDSM_X4T(r0, r1, r2, r3, a) \
    asm volatile("ldmatrix.sync.aligned.m8n8.x4.trans.shared.b16 {%0,%1,%2,%3}, [%4];" \
                 : "=r"(r0), "=r"(r1), "=r"(r2), "=r"(r3) : "r"(a))

__device__ __forceinline__ void mma_f16_f32(float* d, const uint32_t* a, uint32_t b0, uint32_t b1) {
    asm volatile(
        "mma.sync.aligned.m16n8k16.row.col.f32.f16.f16.f32 "
        "{%0,%1,%2,%3}, {%4,%5,%6,%7}, {%8,%9}, {%0,%1,%2,%3};"
        : "+f"(d[0]), "+f"(d[1]), "+f"(d[2]), "+f"(d[3])
        : "r"(a[0]), "r"(a[1]), "r"(a[2]), "r"(a[3]), "r"(b0), "r"(b1));
}

// ---------------- CSR build ----------------
__global__ void k_zero_cnt() {
    int i = blockIdx.x * blockDim.x + threadIdx.x;
    if (i < N_OUTC) { g_cnt[i] = 0; g_fillc[i] = 0; }
    if (i == 0) g_total = 0;
}
__global__ void k_count(const int* __restrict__ row) {
    int i = blockIdx.x * blockDim.x + threadIdx.x;
    if (i < NNZ) atomicAdd(&g_cnt[row[i]], 1);
}
__global__ void k_starts() {
    int i = blockIdx.x * blockDim.x + threadIdx.x;
    if (i < N_OUTC) {
        int c = g_cnt[i];
        g_startv[i] = c ? atomicAdd(&g_total, c) : 0;
    }
}
__global__ void k_fill(const float* __restrict__ vals,
                       const int* __restrict__ row,
                       const int* __restrict__ col) {
    int i = blockIdx.x * blockDim.x + threadIdx.x;
    if (i < NNZ) {
        int r = row[i];
        int pos = g_startv[r] + atomicAdd(&g_fillc[r], 1);
        g_csr_col[pos] = col[i];
        g_csr_val[pos] = vals[i];
    }
}

// ---------------- W prep: [k][n] fp16, XOR-swizzled ----------------
__global__ void k_prepW(const float* __restrict__ W) {
    int i = blockIdx.x * blockDim.x + threadIdx.x;
    if (i >= SS * 64 * 64) return;
    int s = i / 4096, rem = i % 4096;
    int kk = rem / 64, n = rem % 64;
    float w = W[(size_t)(s * 64 + kk) * 64 + n];
    uint32_t sw = swz((uint32_t)kk * 128 + (uint32_t)n * 2);
    *reinterpret_cast<__half*>(g_Bh + (size_t)s * 8192 + sw) = __float2half_rn(w);
}

// ---------------- pooling -> single fp16 plane (2 cols/thread) ----------------
__global__ void k_pool(const float* __restrict__ x) {
    int b = blockIdx.y;
    int r = blockIdx.x * 8 + (threadIdx.x >> 5);
    int c2 = (threadIdx.x & 31) * 2;
    if (r >= N_OUTC) return;
    int s0 = g_startv[r], s1 = s0 + g_cnt[r];
    const float* xb = x + (size_t)b * N_IN * CCH;
    float ax = 0.f, ay = 0.f;
    for (int j = s0; j < s1; ++j) {
        float v = g_csr_val[j];
        float2 xx = *reinterpret_cast<const float2*>(xb + (size_t)g_csr_col[j] * CCH + c2);
        ax += v * xx.x;
        ay += v * xx.y;
    }
    size_t o = ((size_t)b * N_OUTC + r) * CCH + c2;
    *reinterpret_cast<__half2*>(&g_ph[o]) =
        __halves2half2(__float2half_rn(ax), __float2half_rn(ay));
}

// ---------------- HMMA GEMM: 3-stage cp.async pipeline, fp16 ----------------
#define SM_SPW     0            // 128*9*4 = 4608
#define SM_STAGE0  5120
#define ST_B       16384        // A tile 16KB then B 8KB
#define ST_BYTES   24576
#define SM_ALLOC   (SM_STAGE0 + 3 * ST_BYTES + 1024)

__global__ __launch_bounds__(256, 2) void k_gemm(const int* __restrict__ sp,
                                                 const float* __restrict__ bias,
                                                 float* __restrict__ out) {
    extern __shared__ unsigned char smem_raw[];
    uint32_t raw = smem_u32(smem_raw);
    uint32_t sbase = (raw + 1023u) & ~1023u;
    unsigned char* smem = smem_raw + (sbase - raw);

    const int tid  = threadIdx.x;
    const int wid  = tid >> 5;
    const int lane = tid & 31;
    const int bidx = blockIdx.y;
    const int n0   = blockIdx.x * 128;

    const int wm = wid & 3;
    const int wn = wid >> 2;
    const int q  = lane >> 3;
    const int lr = lane & 7;
    const int gid = lane >> 2;
    const int tig = lane & 3;

    // stage spiral indices
    int* spw = reinterpret_cast<int*>(smem + SM_SPW);
    for (int i = tid; i < 128 * SS; i += 256) {
        int r = n0 + i / SS;
        spw[i] = (r < N_OUTC) ? sp[(size_t)r * SS + (i % SS)] : 0;
    }
    __syncthreads();

    const __half* phb = g_ph + (size_t)bidx * N_OUTC * CCH;

    const int grow = tid >> 3;      // 8 threads per 128B row
    const int gch  = tid & 7;

    auto load_stage = [&](int s) {
        uint32_t stg = sbase + SM_STAGE0 + (uint32_t)(s % 3) * ST_BYTES;
#pragma unroll
        for (int it = 0; it < 4; ++it) {
            int row = it * 32 + grow;
            int g = spw[row * SS + s];
            uint32_t d = swz((uint32_t)(row * 128 + gch * 16));
            cp16(stg + d, phb + (size_t)g * CCH + gch * 8);
        }
#pragma unroll
        for (int it = 0; it < 2; ++it) {
            uint32_t o = (uint32_t)(it * 256 + tid) * 16;
            if (o < 8192)
                cp16(stg + ST_B + o, g_Bh + (size_t)s * 8192 + o);
        }
    };

    float acc[2][4][4];
#pragma unroll
    for (int a = 0; a < 2; ++a)
#pragma unroll
        for (int b = 0; b < 4; ++b)
#pragma unroll
            for (int c = 0; c < 4; ++c) acc[a][b][c] = 0.f;

    const int arow_base = wm * 32 + (q & 1) * 8 + lr;
    const int achunk    = (q >> 1) * 16;
    const int bkrow     = (q & 1) * 8 + lr;
    const int bcol_base = (wn * 32 + (q >> 1) * 8) * 2;

    load_stage(0); CP_COMMIT();
    load_stage(1); CP_COMMIT();
    load_stage(2); CP_COMMIT();

    for (int s = 0; s < SS; ++s) {
        CP_WAIT2();
        __syncthreads();

        uint32_t stg = sbase + SM_STAGE0 + (uint32_t)(s % 3) * ST_BYTES;
#pragma unroll
        for (int kk = 0; kk < 4; ++kk) {
            uint32_t ah[2][4], bf[2][4];
#pragma unroll
            for (int mt = 0; mt < 2; ++mt) {
                uint32_t off = swz((uint32_t)((arow_base + mt * 16) * 128 + kk * 32 + achunk));
                LDSM_X4(ah[mt][0], ah[mt][1], ah[mt][2], ah[mt][3], stg + off);
            }
#pragma unroll
            for (int t = 0; t < 2; ++t) {
                uint32_t off = swz((uint32_t)((kk * 16 + bkrow) * 128 + bcol_base + t * 32));
                LDSM_X4T(bf[t][0], bf[t][1], bf[t][2], bf[t][3], stg + ST_B + off);
            }
#pragma unroll
            for (int mt = 0; mt < 2; ++mt)
#pragma unroll
                for (int ni = 0; ni < 4; ++ni) {
                    uint32_t b0 = bf[ni >> 1][(ni & 1) * 2 + 0];
                    uint32_t b1 = bf[ni >> 1][(ni & 1) * 2 + 1];
                    mma_f16_f32(acc[mt][ni], ah[mt], b0, b1);
                }
        }
        __syncthreads();
        if (s + 3 < SS) load_stage(s + 3);
        CP_COMMIT();
    }

    // ---- epilogue: bias + ELU
#pragma unroll
    for (int mt = 0; mt < 2; ++mt) {
#pragma unroll
        for (int half = 0; half < 2; ++half) {
            int r = n0 + wm * 32 + mt * 16 + gid + half * 8;
            if (r < N_OUTC) {
                float* orow = out + ((size_t)bidx * N_OUTC + r) * 64;
#pragma unroll
                for (int ni = 0; ni < 4; ++ni) {
                    int col = wn * 32 + ni * 8 + tig * 2;
                    float2 bb = *reinterpret_cast<const float2*>(bias + col);
                    float vx = acc[mt][ni][half * 2 + 0] + bb.x;
                    float vy = acc[mt][ni][half * 2 + 1] + bb.y;
                    vx = vx > 0.f ? vx : expm1f(vx);
                    vy = vy > 0.f ? vy : expm1f(vy);
                    *reinterpret_cast<float2*>(orow + col) = make_float2(vx, vy);
                }
            }
        }
    }
}

// ---------------- launcher ----------------
extern "C" void kernel_launch(void* const* d_in, const int* in_sizes, int n_in,
                              void* d_out, int out_size) {
    const float* x    = (const float*)d_in[0];
    const float* tval = (const float*)d_in[1];
    const int*   trow = (const int*)d_in[2];
    const int*   tcol = (const int*)d_in[3];
    const int*   sp   = (const int*)d_in[4];
    const float* W    = (const float*)d_in[5];
    const float* bias = (const float*)d_in[6];
    float* out = (float*)d_out;

    cudaFuncSetAttribute(k_gemm, cudaFuncAttributeMaxDynamicSharedMemorySize, SM_ALLOC);

    k_zero_cnt<<<(N_OUTC + 255) / 256, 256>>>();
    k_count<<<(NNZ + 255) / 256, 256>>>(trow);
    k_starts<<<(N_OUTC + 255) / 256, 256>>>();
    k_fill<<<(NNZ + 255) / 256, 256>>>(tval, trow, tcol);
    k_prepW<<<(SS * 64 * 64 + 255) / 256, 256>>>(W);

    dim3 pg((N_OUTC + 7) / 8, BB);
    k_pool<<<pg, 256>>>(x);

    dim3 gg((N_OUTC + 127) / 128, BB);
    k_gemm<<<gg, 256, SM_ALLOC>>>(sp, bias, out);
}

// round 14
// speedup vs baseline: 2.2915x; 1.1253x over previous
#include <cuda_runtime.h>
#include <cuda_fp16.h>
#include <math.h>
#include <stdint.h>

#define BB 16
#define N_IN 6250
#define N_OUTC 25000
#define CCH 64
#define SS 9
#define NNZ 75000

// ---------------- device scratch ----------------
__device__ __align__(16) __half g_ph[(size_t)BB * N_OUTC * CCH]; // pooled fp16 plane
__device__ int   g_cnt[N_OUTC];
__device__ int   g_fillc[N_OUTC];
__device__ int   g_startv[N_OUTC];
__device__ int   g_total;
__device__ int   g_csr_col[NNZ];
__device__ float g_csr_val[NNZ];
// per-slot 64(k)x64(n) fp16 tiles, XOR-swizzled [k][n] layout
__device__ __align__(16) unsigned char g_Bh[SS * 8192];

__device__ __forceinline__ uint32_t smem_u32(const void* p) {
    uint32_t a;
    asm("{ .reg .u64 t; cvta.to.shared.u64 t, %1; cvt.u32.u64 %0, t; }" : "=r"(a) : "l"(p));
    return a;
}
__device__ __forceinline__ uint32_t swz(uint32_t off) { return off ^ ((off >> 3) & 0x70); }

__device__ __forceinline__ void cp16(uint32_t dst, const void* src) {
    asm volatile("cp.async.cg.shared.global [%0], [%1], 16;" :: "r"(dst), "l"(src));
}
#define CP_COMMIT() asm volatile("cp.async.commit_group;" ::: "memory")
#define CP_WAIT1()  asm volatile("cp.async.wait_group 1;" ::: "memory")

#define LDSM_X4(r0, r1, r2, r3, a) \
    asm volatile("ldmatrix.sync.aligned.m8n8.x4.shared.b16 {%0,%1,%2,%3}, [%4];" \
                 : "=r"(r0), "=r"(r1), "=r"(r2), "=r"(r3) : "r"(a))
#define LDSM_X4T(r0, r1, r2, r3, a) \
    asm volatile("ldmatrix.sync.aligned.m8n8.x4.trans.shared.b16 {%0,%1,%2,%3}, [%4];" \
                 : "=r"(r0), "=r"(r1), "=r"(r2), "=r"(r3) : "r"(a))

__device__ __forceinline__ void mma_f16_f32(float* d, const uint32_t* a, uint32_t b0, uint32_t b1) {
    asm volatile(
        "mma.sync.aligned.m16n8k16.row.col.f32.f16.f16.f32 "
        "{%0,%1,%2,%3}, {%4,%5,%6,%7}, {%8,%9}, {%0,%1,%2,%3};"
        : "+f"(d[0]), "+f"(d[1]), "+f"(d[2]), "+f"(d[3])
        : "r"(a[0]), "r"(a[1]), "r"(a[2]), "r"(a[3]), "r"(b0), "r"(b1));
}

// ---------------- CSR build ----------------
__global__ void k_zero_cnt() {
    int i = blockIdx.x * blockDim.x + threadIdx.x;
    if (i < N_OUTC) { g_cnt[i] = 0; g_fillc[i] = 0; }
    if (i == 0) g_total = 0;
}
__global__ void k_count(const int* __restrict__ row) {
    int i = blockIdx.x * blockDim.x + threadIdx.x;
    if (i < NNZ) atomicAdd(&g_cnt[row[i]], 1);
}
__global__ void k_starts() {
    int i = blockIdx.x * blockDim.x + threadIdx.x;
    if (i < N_OUTC) {
        int c = g_cnt[i];
        g_startv[i] = c ? atomicAdd(&g_total, c) : 0;
    }
}
__global__ void k_fill(const float* __restrict__ vals,
                       const int* __restrict__ row,
                       const int* __restrict__ col) {
    int i = blockIdx.x * blockDim.x + threadIdx.x;
    if (i < NNZ) {
        int r = row[i];
        int pos = g_startv[r] + atomicAdd(&g_fillc[r], 1);
        g_csr_col[pos] = col[i];
        g_csr_val[pos] = vals[i];
    }
}

// ---------------- W prep: [k][n] fp16, XOR-swizzled ----------------
__global__ void k_prepW(const float* __restrict__ W) {
    int i = blockIdx.x * blockDim.x + threadIdx.x;
    if (i >= SS * 64 * 64) return;
    int s = i / 4096, rem = i % 4096;
    int kk = rem / 64, n = rem % 64;
    float w = W[(size_t)(s * 64 + kk) * 64 + n];
    uint32_t sw = swz((uint32_t)kk * 128 + (uint32_t)n * 2);
    *reinterpret_cast<__half*>(g_Bh + (size_t)s * 8192 + sw) = __float2half_rn(w);
}

// ---------------- pooling -> fp16 plane (4 cols/thread, float4 loads) ----------------
__global__ void k_pool(const float* __restrict__ x) {
    int b = blockIdx.y;
    int r = blockIdx.x * 16 + (threadIdx.x >> 4);
    int c4 = (threadIdx.x & 15) * 4;
    if (r >= N_OUTC) return;
    int s0 = g_startv[r], s1 = s0 + g_cnt[r];
    const float* xb = x + (size_t)b * N_IN * CCH;
    float a0 = 0.f, a1 = 0.f, a2 = 0.f, a3 = 0.f;
    for (int j = s0; j < s1; ++j) {
        float v = g_csr_val[j];
        float4 xx = *reinterpret_cast<const float4*>(xb + (size_t)g_csr_col[j] * CCH + c4);
        a0 += v * xx.x; a1 += v * xx.y; a2 += v * xx.z; a3 += v * xx.w;
    }
    size_t o = ((size_t)b * N_OUTC + r) * CCH + c4;
    __half2 h0 = __halves2half2(__float2half_rn(a0), __float2half_rn(a1));
    __half2 h1 = __halves2half2(__float2half_rn(a2), __float2half_rn(a3));
    *reinterpret_cast<uint2*>(&g_ph[o]) =
        make_uint2(*reinterpret_cast<uint32_t*>(&h0), *reinterpret_cast<uint32_t*>(&h1));
}

// ---------------- HMMA GEMM: M-tile 256, 2-stage cp.async pipeline ----------------
#define SM_SPW     0            // 256*9*4 = 9216
#define SM_STAGE0  9216
#define ST_B       32768        // A tile 32KB then B 8KB
#define ST_BYTES   40960
#define SM_ALLOC   (SM_STAGE0 + 2 * ST_BYTES + 1024)

__global__ __launch_bounds__(256, 2) void k_gemm(const int* __restrict__ sp,
                                                 const float* __restrict__ bias,
                                                 float* __restrict__ out) {
    extern __shared__ unsigned char smem_raw[];
    uint32_t raw = smem_u32(smem_raw);
    uint32_t sbase = (raw + 1023u) & ~1023u;
    unsigned char* smem = smem_raw + (sbase - raw);

    const int tid  = threadIdx.x;
    const int wid  = tid >> 5;      // 0..7 : M warp tile (32 rows each)
    const int lane = tid & 31;
    const int bidx = blockIdx.y;
    const int n0   = blockIdx.x * 256;

    const int q  = lane >> 3;
    const int lr = lane & 7;
    const int gid = lane >> 2;
    const int tig = lane & 3;

    // stage spiral indices (clamped)
    int* spw = reinterpret_cast<int*>(smem + SM_SPW);
    for (int i = tid; i < 256 * SS; i += 256) {
        int r = n0 + i / SS;
        spw[i] = (r < N_OUTC) ? sp[(size_t)r * SS + (i % SS)] : 0;
    }
    __syncthreads();

    const __half* phb = g_ph + (size_t)bidx * N_OUTC * CCH;

    const int grow = tid >> 3;      // 8 threads per 128B row, 32 rows/iter
    const int gch  = tid & 7;

    auto load_stage = [&](int s, int buf) {
        uint32_t stg = sbase + SM_STAGE0 + (uint32_t)buf * ST_BYTES;
#pragma unroll
        for (int it = 0; it < 8; ++it) {
            int row = it * 32 + grow;
            int g = spw[row * SS + s];
            uint32_t d = swz((uint32_t)(row * 128 + gch * 16));
            cp16(stg + d, phb + (size_t)g * CCH + gch * 8);
        }
#pragma unroll
        for (int it = 0; it < 2; ++it) {
            uint32_t o = (uint32_t)(it * 256 + tid) * 16;
            if (o < 8192)
                cp16(stg + ST_B + o, g_Bh + (size_t)s * 8192 + o);
        }
    };

    float acc[2][8][4];   // 2 m16-frags x 8 n8-frags
#pragma unroll
    for (int a = 0; a < 2; ++a)
#pragma unroll
        for (int b = 0; b < 8; ++b)
#pragma unroll
            for (int c = 0; c < 4; ++c) acc[a][b][c] = 0.f;

    const int arow_base = wid * 32 + (q & 1) * 8 + lr;
    const int achunk    = (q >> 1) * 16;
    const int bkrow     = (q & 1) * 8 + lr;
    const int bcol_base = ((q >> 1) * 8) * 2;

    load_stage(0, 0); CP_COMMIT();
    load_stage(1, 1); CP_COMMIT();

    for (int s = 0; s < SS; ++s) {
        CP_WAIT1();
        __syncthreads();

        uint32_t stg = sbase + SM_STAGE0 + (uint32_t)(s & 1) * ST_BYTES;
#pragma unroll
        for (int kk = 0; kk < 4; ++kk) {
            uint32_t ah[2][4], bf[4][4];
#pragma unroll
            for (int mt = 0; mt < 2; ++mt) {
                uint32_t off = swz((uint32_t)((arow_base + mt * 16) * 128 + kk * 32 + achunk));
                LDSM_X4(ah[mt][0], ah[mt][1], ah[mt][2], ah[mt][3], stg + off);
            }
#pragma unroll
            for (int t = 0; t < 4; ++t) {
                uint32_t off = swz((uint32_t)((kk * 16 + bkrow) * 128 + bcol_base + t * 32));
                LDSM_X4T(bf[t][0], bf[t][1], bf[t][2], bf[t][3], stg + ST_B + off);
            }
#pragma unroll
            for (int mt = 0; mt < 2; ++mt)
#pragma unroll
                for (int ni = 0; ni < 8; ++ni) {
                    uint32_t b0 = bf[ni >> 1][(ni & 1) * 2 + 0];
                    uint32_t b1 = bf[ni >> 1][(ni & 1) * 2 + 1];
                    mma_f16_f32(acc[mt][ni], ah[mt], b0, b1);
                }
        }
        __syncthreads();
        if (s + 2 < SS) load_stage(s + 2, s & 1);
        CP_COMMIT();
    }

    // ---- epilogue: bias + ELU
#pragma unroll
    for (int mt = 0; mt < 2; ++mt) {
#pragma unroll
        for (int half = 0; half < 2; ++half) {
            int r = n0 + wid * 32 + mt * 16 + gid + half * 8;
            if (r < N_OUTC) {
                float* orow = out + ((size_t)bidx * N_OUTC + r) * 64;
#pragma unroll
                for (int ni = 0; ni < 8; ++ni) {
                    int col = ni * 8 + tig * 2;
                    float2 bb = *reinterpret_cast<const float2*>(bias + col);
                    float vx = acc[mt][ni][half * 2 + 0] + bb.x;
                    float vy = acc[mt][ni][half * 2 + 1] + bb.y;
                    vx = vx > 0.f ? vx : expm1f(vx);
                    vy = vy > 0.f ? vy : expm1f(vy);
                    *reinterpret_cast<float2*>(orow + col) = make_float2(vx, vy);
                }
            }
        }
    }
}

// ---------------- launcher ----------------
extern "C" void kernel_launch(void* const* d_in, const int* in_sizes, int n_in,
                              void* d_out, int out_size) {
    const float* x    = (const float*)d_in[0];
    const float* tval = (const float*)d_in[1];
    const int*   trow = (const int*)d_in[2];
    const int*   tcol = (const int*)d_in[3];
    const int*   sp   = (const int*)d_in[4];
    const float* W    = (const float*)d_in[5];
    const float* bias = (const float*)d_in[6];
    float* out = (float*)d_out;

    cudaFuncSetAttribute(k_gemm, cudaFuncAttributeMaxDynamicSharedMemorySize, SM_ALLOC);

    k_zero_cnt<<<(N_OUTC + 255) / 256, 256>>>();
    k_count<<<(NNZ + 255) / 256, 256>>>(trow);
    k_starts<<<(N_OUTC + 255) / 256, 256>>>();
    k_fill<<<(NNZ + 255) / 256, 256>>>(tval, trow, tcol);
    k_prepW<<<(SS * 64 * 64 + 255) / 256, 256>>>(W);

    dim3 pg((N_OUTC + 15) / 16, BB);
    k_pool<<<pg, 256>>>(x);

    dim3 gg((N_OUTC + 255) / 256, BB);
    k_gemm<<<gg, 256, SM_ALLOC>>>(sp, bias, out);
}